// round 9
// baseline (speedup 1.0000x reference)
#include <cuda_runtime.h>
#include <math.h>

// SafetyConstraint CBF: out = clip(clip(grad(h).sdot,-100,100) + 2h, -20, 20)
// R9: best-of-breed merge. R5's exact memory path (plain cp.async.cg 16B,
// two 128-row stages, plain stores — measured 6.08 TB/s, the BW champion)
// + rsqrt quat-normalize (40 regs) + launch_bounds(128,12) for 12 resident
// blocks/SM. No L2 hints, no streaming stores (both regressed BW in R8).

#define TPB 128
#define SROWS 128                 // rows per stage
#define SF (SROWS * 18)           // 2304 floats = 9216 B per stage
#define RPB (SROWS * 2)           // 256 rows per block

__device__ __forceinline__ float cbf_row(const float* __restrict__ r, float act0)
{
    const float px = r[0],  py = r[1],  pz = r[2];
    const float qw = r[3],  qx = r[4],  qy = r[5],  qz = r[6];
    const float vx = r[7],  vy = r[8],  vz = r[9];
    const float wx = r[10], wy = r[11], wz = r[12];

    const float thrust = fminf(fmaxf(act0, 0.0f), 0.35f);

    // quat normalize via rsqrt (+1st-order eps correction; err ~1e-16
    // vs reference's 1/(nrm+1e-8))
    const float nsq = qw*qw + qx*qx + qy*qy + qz*qz;
    const float rs = rsqrtf(nsq);                 // 1/nrm
    const float inv = rs - 1e-8f * rs * rs;       // ~ 1/(nrm+1e-8)
    const float uw = qw * inv, ux = qx * inv, uy = qy * inv, uz = qz * inv;

    const float b0 = pz - 0.4f;
    const float b1 = 1.6f - pz;
    const float b2 = 1.0f - px * px;
    const float b3 = 1.0f - py * py;
    const float b4 = 0.16f - (vx*vx + vy*vy + vz*vz);
    const float aq = fabsf(uw);
    const float qc = fminf(fmaxf(aq, 0.1f), 1.0f);
    const float b5 = qc - 0.75f;

    const float BETA = 5.0f;
    const float bmin = fminf(fminf(fminf(b0, b1), fminf(b2, b3)), fminf(b4, b5));
    const float e0 = __expf(-BETA * (b0 - bmin));
    const float e1 = __expf(-BETA * (b1 - bmin));
    const float e2 = __expf(-BETA * (b2 - bmin));
    const float e3 = __expf(-BETA * (b3 - bmin));
    const float e4 = __expf(-BETA * (b4 - bmin));
    const float e5 = __expf(-BETA * (b5 - bmin));
    const float S = e0 + e1 + e2 + e3 + e4 + e5;
    const float invS = 1.0f / S;
    const float h = bmin - __logf(S) * (1.0f / BETA);

    const float p0 = e0 * invS, p1 = e1 * invS, p2 = e2 * invS;
    const float p3 = e3 * invS, p4 = e4 * invS, p5 = e5 * invS;

    const float gpx = -2.0f * px * p2;
    const float gpy = -2.0f * py * p3;
    const float gpz = p0 - p1;
    const float gvz = -2.0f * p4 * vz;

    const float active = (aq > 0.1f && aq < 1.0f) ? 1.0f : 0.0f;
    const float sgn = (uw >= 0.0f) ? 1.0f : -1.0f;
    const float coef = p5 * sgn * active;
    const float common = coef * uw * inv * rs;
    const float gq0 = coef * inv - common * qw;
    const float gq1 = -common * qx;
    const float gq2 = -common * qy;
    const float gq3 = -common * qz;

    const float qd0 = 0.5f * (-ux * wx - uy * wy - uz * wz);
    const float qd1 = 0.5f * ( uw * wx + uy * wz - uz * wy);
    const float qd2 = 0.5f * ( uw * wy + uz * wx - ux * wz);
    const float qd3 = 0.5f * ( uw * wz + ux * wy - uy * wx);
    float R33 = 1.0f - 2.0f * (ux * ux + uy * uy);
    R33 = fminf(fmaxf(R33, -1.0f), 1.0f);
    const float az = thrust * R33 * (1.0f / 0.027f) - 9.81f;

    float lie = gpx * vx + gpy * vy + gpz * vz;
    lie += gq0 * qd0 + gq1 * qd1 + gq2 * qd2 + gq3 * qd3;
    lie += gvz * az;

    const float h_dot = fminf(fmaxf(lie, -100.0f), 100.0f);
    return fminf(fmaxf(h_dot + 2.0f * h, -20.0f), 20.0f);
}

// Stage one 128-row chunk: 576 float4 = 4.5/thread (5th trip predicated).
// Plain cp.async.cg — the exact request path that measured 6.08 TB/s.
__device__ __forceinline__ void issue_stage(float* sdst, const float* __restrict__ gsrc)
{
    unsigned dst_base = (unsigned)__cvta_generic_to_shared(sdst);
    const float4* g4 = reinterpret_cast<const float4*>(gsrc);
    #pragma unroll
    for (int k = 0; k < 5; k++) {
        int i = threadIdx.x + k * TPB;
        if (i < SF / 4) {
            unsigned dst = dst_base + i * 16u;
            asm volatile("cp.async.cg.shared.global [%0], [%1], 16;\n"
                         :: "r"(dst), "l"(g4 + i));
        }
    }
    asm volatile("cp.async.commit_group;\n" ::: "memory");
}

__global__ __launch_bounds__(TPB, 12) void cbf_kernel(
    const float* __restrict__ state,   // [n, 18]
    const float* __restrict__ action,  // [n, 4]
    float* __restrict__ out,           // [n]
    int n)
{
    __shared__ float s[2][SF];         // 18432 B

    const int base = blockIdx.x * RPB;
    const int tid = threadIdx.x;

    if (base + RPB <= n) {
        // Both stages in flight immediately: 18.4 KB per block.
        issue_stage(s[0], state + (size_t)base * 18);
        issue_stage(s[1], state + (size_t)(base + SROWS) * 18);

        // Thrust loads — latency hides under the cp.async drain.
        const int r0 = base + tid;
        const int r1 = base + SROWS + tid;
        const float a0 = __ldg(action + (size_t)r0 * 4);
        const float a1 = __ldg(action + (size_t)r1 * 4);

        // Stage A ready; stage B still in flight during compute of A.
        asm volatile("cp.async.wait_group 1;\n" ::: "memory");
        __syncthreads();

        out[r0] = cbf_row(&s[0][tid * 18], a0);

        asm volatile("cp.async.wait_group 0;\n" ::: "memory");
        __syncthreads();

        out[r1] = cbf_row(&s[1][tid * 18], a1);
    } else {
        // Tail block: guarded scalar staging + compute.
        int cnt = n - base;
        if (cnt < 0) cnt = 0;
        float* sf = &s[0][0];
        for (int i = tid; i < cnt * 18; i += TPB) {
            sf[i] = state[(size_t)base * 18 + i];   // cnt*18 <= 2*SF
        }
        __syncthreads();
        for (int l = tid; l < cnt; l += TPB) {
            const int row = base + l;
            const float a0 = action[(size_t)row * 4];
            out[row] = cbf_row(sf + l * 18, a0);
        }
    }
}

extern "C" void kernel_launch(void* const* d_in, const int* in_sizes, int n_in,
                              void* d_out, int out_size)
{
    const float* state  = (const float*)d_in[0];
    const float* action = (const float*)d_in[1];
    float* out = (float*)d_out;

    const int n = out_size;
    const int grid = (n + RPB - 1) / RPB;
    cbf_kernel<<<grid, TPB>>>(state, action, out, n);
}

// round 10
// speedup vs baseline: 1.0096x; 1.0096x over previous
#include <cuda_runtime.h>
#include <math.h>

// SafetyConstraint CBF: out = clip(clip(grad(h).sdot,-100,100) + 2h, -20, 20)
// R10: single-variable test on top of R9 (best-of-breed two-stage cp.async,
// 128-row stages, 12 blocks/SM): add __stcs streaming stores ONLY (the
// half of R8's change-pair plausibly responsible for its best wall time).
// Kernel is at the measured LTS throughput ceiling (~6.1 TB/s for 193 MB
// mandatory traffic); this is a convergence-region refinement.

#define TPB 128
#define SROWS 128                 // rows per stage
#define SF (SROWS * 18)           // 2304 floats = 9216 B per stage
#define RPB (SROWS * 2)           // 256 rows per block

__device__ __forceinline__ float cbf_row(const float* __restrict__ r, float act0)
{
    const float px = r[0],  py = r[1],  pz = r[2];
    const float qw = r[3],  qx = r[4],  qy = r[5],  qz = r[6];
    const float vx = r[7],  vy = r[8],  vz = r[9];
    const float wx = r[10], wy = r[11], wz = r[12];

    const float thrust = fminf(fmaxf(act0, 0.0f), 0.35f);

    // quat normalize via rsqrt (+1st-order eps correction; err ~1e-16
    // vs reference's 1/(nrm+1e-8))
    const float nsq = qw*qw + qx*qx + qy*qy + qz*qz;
    const float rs = rsqrtf(nsq);                 // 1/nrm
    const float inv = rs - 1e-8f * rs * rs;       // ~ 1/(nrm+1e-8)
    const float uw = qw * inv, ux = qx * inv, uy = qy * inv, uz = qz * inv;

    const float b0 = pz - 0.4f;
    const float b1 = 1.6f - pz;
    const float b2 = 1.0f - px * px;
    const float b3 = 1.0f - py * py;
    const float b4 = 0.16f - (vx*vx + vy*vy + vz*vz);
    const float aq = fabsf(uw);
    const float qc = fminf(fmaxf(aq, 0.1f), 1.0f);
    const float b5 = qc - 0.75f;

    const float BETA = 5.0f;
    const float bmin = fminf(fminf(fminf(b0, b1), fminf(b2, b3)), fminf(b4, b5));
    const float e0 = __expf(-BETA * (b0 - bmin));
    const float e1 = __expf(-BETA * (b1 - bmin));
    const float e2 = __expf(-BETA * (b2 - bmin));
    const float e3 = __expf(-BETA * (b3 - bmin));
    const float e4 = __expf(-BETA * (b4 - bmin));
    const float e5 = __expf(-BETA * (b5 - bmin));
    const float S = e0 + e1 + e2 + e3 + e4 + e5;
    const float invS = 1.0f / S;
    const float h = bmin - __logf(S) * (1.0f / BETA);

    const float p0 = e0 * invS, p1 = e1 * invS, p2 = e2 * invS;
    const float p3 = e3 * invS, p4 = e4 * invS, p5 = e5 * invS;

    const float gpx = -2.0f * px * p2;
    const float gpy = -2.0f * py * p3;
    const float gpz = p0 - p1;
    const float gvz = -2.0f * p4 * vz;

    const float active = (aq > 0.1f && aq < 1.0f) ? 1.0f : 0.0f;
    const float sgn = (uw >= 0.0f) ? 1.0f : -1.0f;
    const float coef = p5 * sgn * active;
    const float common = coef * uw * inv * rs;
    const float gq0 = coef * inv - common * qw;
    const float gq1 = -common * qx;
    const float gq2 = -common * qy;
    const float gq3 = -common * qz;

    const float qd0 = 0.5f * (-ux * wx - uy * wy - uz * wz);
    const float qd1 = 0.5f * ( uw * wx + uy * wz - uz * wy);
    const float qd2 = 0.5f * ( uw * wy + uz * wx - ux * wz);
    const float qd3 = 0.5f * ( uw * wz + ux * wy - uy * wx);
    float R33 = 1.0f - 2.0f * (ux * ux + uy * uy);
    R33 = fminf(fmaxf(R33, -1.0f), 1.0f);
    const float az = thrust * R33 * (1.0f / 0.027f) - 9.81f;

    float lie = gpx * vx + gpy * vy + gpz * vz;
    lie += gq0 * qd0 + gq1 * qd1 + gq2 * qd2 + gq3 * qd3;
    lie += gvz * az;

    const float h_dot = fminf(fmaxf(lie, -100.0f), 100.0f);
    return fminf(fmaxf(h_dot + 2.0f * h, -20.0f), 20.0f);
}

// Stage one 128-row chunk: 576 float4 = 4.5/thread (5th trip predicated).
// Plain cp.async.cg — the request path that measured best BW.
__device__ __forceinline__ void issue_stage(float* sdst, const float* __restrict__ gsrc)
{
    unsigned dst_base = (unsigned)__cvta_generic_to_shared(sdst);
    const float4* g4 = reinterpret_cast<const float4*>(gsrc);
    #pragma unroll
    for (int k = 0; k < 5; k++) {
        int i = threadIdx.x + k * TPB;
        if (i < SF / 4) {
            unsigned dst = dst_base + i * 16u;
            asm volatile("cp.async.cg.shared.global [%0], [%1], 16;\n"
                         :: "r"(dst), "l"(g4 + i));
        }
    }
    asm volatile("cp.async.commit_group;\n" ::: "memory");
}

__global__ __launch_bounds__(TPB, 12) void cbf_kernel(
    const float* __restrict__ state,   // [n, 18]
    const float* __restrict__ action,  // [n, 4]
    float* __restrict__ out,           // [n]
    int n)
{
    __shared__ float s[2][SF];         // 18432 B

    const int base = blockIdx.x * RPB;
    const int tid = threadIdx.x;

    if (base + RPB <= n) {
        // Both stages in flight immediately: 18.4 KB per block.
        issue_stage(s[0], state + (size_t)base * 18);
        issue_stage(s[1], state + (size_t)(base + SROWS) * 18);

        // Thrust loads — latency hides under the cp.async drain.
        const int r0 = base + tid;
        const int r1 = base + SROWS + tid;
        const float a0 = __ldg(action + (size_t)r0 * 4);
        const float a1 = __ldg(action + (size_t)r1 * 4);

        // Stage A ready; stage B still in flight during compute of A.
        asm volatile("cp.async.wait_group 1;\n" ::: "memory");
        __syncthreads();

        __stcs(out + r0, cbf_row(&s[0][tid * 18], a0));

        asm volatile("cp.async.wait_group 0;\n" ::: "memory");
        __syncthreads();

        __stcs(out + r1, cbf_row(&s[1][tid * 18], a1));
    } else {
        // Tail block: guarded scalar staging + compute.
        int cnt = n - base;
        if (cnt < 0) cnt = 0;
        float* sf = &s[0][0];
        for (int i = tid; i < cnt * 18; i += TPB) {
            sf[i] = state[(size_t)base * 18 + i];   // cnt*18 <= 2*SF
        }
        __syncthreads();
        for (int l = tid; l < cnt; l += TPB) {
            const int row = base + l;
            const float a0 = action[(size_t)row * 4];
            out[row] = cbf_row(sf + l * 18, a0);
        }
    }
}

extern "C" void kernel_launch(void* const* d_in, const int* in_sizes, int n_in,
                              void* d_out, int out_size)
{
    const float* state  = (const float*)d_in[0];
    const float* action = (const float*)d_in[1];
    float* out = (float*)d_out;

    const int n = out_size;
    const int grid = (n + RPB - 1) / RPB;
    cbf_kernel<<<grid, TPB>>>(state, action, out, n);
}

// round 11
// speedup vs baseline: 1.0173x; 1.0077x over previous
#include <cuda_runtime.h>
#include <math.h>

// SafetyConstraint CBF: out = clip(clip(grad(h).sdot,-100,100) + 2h, -20, 20)
// R11: pin the R5 occupancy sweet spot. Cross-round analysis shows DRAM BW
// tracks L1D-remaining (228KB - smem in use): 10 blocks/SM x 18.4KB = 184KB
// smem -> 44KB L1D -> 76.8% DRAM (best); 12 blocks -> 221KB smem -> 7KB L1D
// -> 73% (action LDGs + stores thrash L1). So: launch_bounds(128,10),
// R5's verbatim memory path (plain cp.async.cg, plain stores), rsqrt
// normalize to keep regs at 40.

#define TPB 128
#define SROWS 128                 // rows per stage
#define SF (SROWS * 18)           // 2304 floats = 9216 B per stage
#define RPB (SROWS * 2)           // 256 rows per block

__device__ __forceinline__ float cbf_row(const float* __restrict__ r, float act0)
{
    const float px = r[0],  py = r[1],  pz = r[2];
    const float qw = r[3],  qx = r[4],  qy = r[5],  qz = r[6];
    const float vx = r[7],  vy = r[8],  vz = r[9];
    const float wx = r[10], wy = r[11], wz = r[12];

    const float thrust = fminf(fmaxf(act0, 0.0f), 0.35f);

    // quat normalize via rsqrt (+1st-order eps correction; err ~1e-16
    // vs reference's 1/(nrm+1e-8))
    const float nsq = qw*qw + qx*qx + qy*qy + qz*qz;
    const float rs = rsqrtf(nsq);                 // 1/nrm
    const float inv = rs - 1e-8f * rs * rs;       // ~ 1/(nrm+1e-8)
    const float uw = qw * inv, ux = qx * inv, uy = qy * inv, uz = qz * inv;

    const float b0 = pz - 0.4f;
    const float b1 = 1.6f - pz;
    const float b2 = 1.0f - px * px;
    const float b3 = 1.0f - py * py;
    const float b4 = 0.16f - (vx*vx + vy*vy + vz*vz);
    const float aq = fabsf(uw);
    const float qc = fminf(fmaxf(aq, 0.1f), 1.0f);
    const float b5 = qc - 0.75f;

    const float BETA = 5.0f;
    const float bmin = fminf(fminf(fminf(b0, b1), fminf(b2, b3)), fminf(b4, b5));
    const float e0 = __expf(-BETA * (b0 - bmin));
    const float e1 = __expf(-BETA * (b1 - bmin));
    const float e2 = __expf(-BETA * (b2 - bmin));
    const float e3 = __expf(-BETA * (b3 - bmin));
    const float e4 = __expf(-BETA * (b4 - bmin));
    const float e5 = __expf(-BETA * (b5 - bmin));
    const float S = e0 + e1 + e2 + e3 + e4 + e5;
    const float invS = 1.0f / S;
    const float h = bmin - __logf(S) * (1.0f / BETA);

    const float p0 = e0 * invS, p1 = e1 * invS, p2 = e2 * invS;
    const float p3 = e3 * invS, p4 = e4 * invS, p5 = e5 * invS;

    const float gpx = -2.0f * px * p2;
    const float gpy = -2.0f * py * p3;
    const float gpz = p0 - p1;
    const float gvz = -2.0f * p4 * vz;

    const float active = (aq > 0.1f && aq < 1.0f) ? 1.0f : 0.0f;
    const float sgn = (uw >= 0.0f) ? 1.0f : -1.0f;
    const float coef = p5 * sgn * active;
    const float common = coef * uw * inv * rs;
    const float gq0 = coef * inv - common * qw;
    const float gq1 = -common * qx;
    const float gq2 = -common * qy;
    const float gq3 = -common * qz;

    const float qd0 = 0.5f * (-ux * wx - uy * wy - uz * wz);
    const float qd1 = 0.5f * ( uw * wx + uy * wz - uz * wy);
    const float qd2 = 0.5f * ( uw * wy + uz * wx - ux * wz);
    const float qd3 = 0.5f * ( uw * wz + ux * wy - uy * wx);
    float R33 = 1.0f - 2.0f * (ux * ux + uy * uy);
    R33 = fminf(fmaxf(R33, -1.0f), 1.0f);
    const float az = thrust * R33 * (1.0f / 0.027f) - 9.81f;

    float lie = gpx * vx + gpy * vy + gpz * vz;
    lie += gq0 * qd0 + gq1 * qd1 + gq2 * qd2 + gq3 * qd3;
    lie += gvz * az;

    const float h_dot = fminf(fmaxf(lie, -100.0f), 100.0f);
    return fminf(fmaxf(h_dot + 2.0f * h, -20.0f), 20.0f);
}

// Stage one 128-row chunk: 576 float4 = 4.5/thread (5th trip predicated).
// Plain cp.async.cg — the exact request path that measured 6.08 TB/s.
__device__ __forceinline__ void issue_stage(float* sdst, const float* __restrict__ gsrc)
{
    unsigned dst_base = (unsigned)__cvta_generic_to_shared(sdst);
    const float4* g4 = reinterpret_cast<const float4*>(gsrc);
    #pragma unroll
    for (int k = 0; k < 5; k++) {
        int i = threadIdx.x + k * TPB;
        if (i < SF / 4) {
            unsigned dst = dst_base + i * 16u;
            asm volatile("cp.async.cg.shared.global [%0], [%1], 16;\n"
                         :: "r"(dst), "l"(g4 + i));
        }
    }
    asm volatile("cp.async.commit_group;\n" ::: "memory");
}

__global__ __launch_bounds__(TPB, 10) void cbf_kernel(
    const float* __restrict__ state,   // [n, 18]
    const float* __restrict__ action,  // [n, 4]
    float* __restrict__ out,           // [n]
    int n)
{
    __shared__ float s[2][SF];         // 18432 B

    const int base = blockIdx.x * RPB;
    const int tid = threadIdx.x;

    if (base + RPB <= n) {
        // Both stages in flight immediately: 18.4 KB per block.
        issue_stage(s[0], state + (size_t)base * 18);
        issue_stage(s[1], state + (size_t)(base + SROWS) * 18);

        // Thrust loads — latency hides under the cp.async drain.
        const int r0 = base + tid;
        const int r1 = base + SROWS + tid;
        const float a0 = __ldg(action + (size_t)r0 * 4);
        const float a1 = __ldg(action + (size_t)r1 * 4);

        // Stage A ready; stage B still in flight during compute of A.
        asm volatile("cp.async.wait_group 1;\n" ::: "memory");
        __syncthreads();

        out[r0] = cbf_row(&s[0][tid * 18], a0);

        asm volatile("cp.async.wait_group 0;\n" ::: "memory");
        __syncthreads();

        out[r1] = cbf_row(&s[1][tid * 18], a1);
    } else {
        // Tail block: guarded scalar staging + compute.
        int cnt = n - base;
        if (cnt < 0) cnt = 0;
        float* sf = &s[0][0];
        for (int i = tid; i < cnt * 18; i += TPB) {
            sf[i] = state[(size_t)base * 18 + i];   // cnt*18 <= 2*SF
        }
        __syncthreads();
        for (int l = tid; l < cnt; l += TPB) {
            const int row = base + l;
            const float a0 = action[(size_t)row * 4];
            out[row] = cbf_row(sf + l * 18, a0);
        }
    }
}

extern "C" void kernel_launch(void* const* d_in, const int* in_sizes, int n_in,
                              void* d_out, int out_size)
{
    const float* state  = (const float*)d_in[0];
    const float* action = (const float*)d_in[1];
    float* out = (float*)d_out;

    const int n = out_size;
    const int grid = (n + RPB - 1) / RPB;
    cbf_kernel<<<grid, TPB>>>(state, action, out, n);
}